// round 1
// baseline (speedup 1.0000x reference)
#include <cuda_runtime.h>

// ---------------------------------------------------------------------------
// SpatialAttention: q = Wq@p + bq ; k = Wk@b + bk ; E = qT k ; A = softmax(E)
// out[b,c,n] = sum_m A[n,m] * b[b,c,m]
// B=4, C_in=256, C_out=128, N=H*W=4096
// ---------------------------------------------------------------------------

#define BATCH 4
#define CIN   256
#define COUT  128
#define NTOK  4096

#define TILE  128
#define BK    8
#define TPAD  4          // smem row stride = 132 floats

// Scratch (allocation-free rule: __device__ globals)
__device__ float g_q  [(long long)BATCH * COUT * NTOK];            // [b][o][n]
__device__ float g_k  [(long long)BATCH * COUT * NTOK];            // [b][o][n]
__device__ float g_att[(long long)BATCH * NTOK * NTOK];            // [b][n][m]

// ---------------------------------------------------------------------------
// Generic tiled SGEMM:  C[m', n'] = sum_k A(m',k) * B(n',k)  (+ bias[m'])
//   A_KMAJ: A stored row-major [M][K] (k contiguous)  -> transpose on smem load
//          else A stored [K][M] (m contiguous)        -> direct copy
//   B_KMAJ: same convention for B ([N][K] vs [K][N])
// C stored row-major [M][N] (n contiguous). All dims multiples of tile sizes.
// ---------------------------------------------------------------------------
template<bool A_KMAJ, bool B_KMAJ, bool HAS_BIAS>
__global__ __launch_bounds__(256, 2)
void sgemm_nt(const float* __restrict__ A, const float* __restrict__ B,
              const float* __restrict__ bias, float* __restrict__ C,
              int M, int N, int K,
              long long strideA, long long strideB, long long strideC)
{
    __shared__ float As[BK][TILE + TPAD];
    __shared__ float Bs[BK][TILE + TPAD];

    A += (long long)blockIdx.z * strideA;
    B += (long long)blockIdx.z * strideB;
    C += (long long)blockIdx.z * strideC;

    const int m0  = blockIdx.x * TILE;
    const int n0  = blockIdx.y * TILE;
    const int tid = threadIdx.x;
    const int tx  = tid & 15;   // n micro index
    const int ty  = tid >> 4;   // m micro index

    float acc[8][8];
#pragma unroll
    for (int i = 0; i < 8; i++)
#pragma unroll
        for (int j = 0; j < 8; j++) acc[i][j] = 0.f;

    for (int k0 = 0; k0 < K; k0 += BK) {
        // ---- load A tile into As[k][m] ----
        if (A_KMAJ) {
            const int row = tid >> 1;
            const int kq  = (tid & 1) * 4;
            float4 v = *(const float4*)(A + (long long)(m0 + row) * K + k0 + kq);
            As[kq + 0][row] = v.x; As[kq + 1][row] = v.y;
            As[kq + 2][row] = v.z; As[kq + 3][row] = v.w;
        } else {
            const int k  = tid >> 5;
            const int m4 = (tid & 31) * 4;
            *(float4*)&As[k][m4] =
                *(const float4*)(A + (long long)(k0 + k) * M + m0 + m4);
        }
        // ---- load B tile into Bs[k][n] ----
        if (B_KMAJ) {
            const int row = tid >> 1;
            const int kq  = (tid & 1) * 4;
            float4 v = *(const float4*)(B + (long long)(n0 + row) * K + k0 + kq);
            Bs[kq + 0][row] = v.x; Bs[kq + 1][row] = v.y;
            Bs[kq + 2][row] = v.z; Bs[kq + 3][row] = v.w;
        } else {
            const int k  = tid >> 5;
            const int n4 = (tid & 31) * 4;
            *(float4*)&Bs[k][n4] =
                *(const float4*)(B + (long long)(k0 + k) * N + n0 + n4);
        }
        __syncthreads();

#pragma unroll
        for (int kk = 0; kk < BK; kk++) {
            float a[8], bb[8];
            *(float4*)(a)      = *(const float4*)&As[kk][ty * 8];
            *(float4*)(a + 4)  = *(const float4*)&As[kk][ty * 8 + 4];
            *(float4*)(bb)     = *(const float4*)&Bs[kk][tx * 8];
            *(float4*)(bb + 4) = *(const float4*)&Bs[kk][tx * 8 + 4];
#pragma unroll
            for (int i = 0; i < 8; i++)
#pragma unroll
                for (int j = 0; j < 8; j++)
                    acc[i][j] += a[i] * bb[j];
        }
        __syncthreads();
    }

    // ---- epilogue: contiguous vec4 stores along n ----
#pragma unroll
    for (int i = 0; i < 8; i++) {
        const int m  = m0 + ty * 8 + i;
        const float bv = HAS_BIAS ? bias[m] : 0.f;
        float* crow = C + (long long)m * N + n0 + tx * 8;
#pragma unroll
        for (int j = 0; j < 8; j += 4) {
            float4 v;
            v.x = acc[i][j + 0] + bv;
            v.y = acc[i][j + 1] + bv;
            v.z = acc[i][j + 2] + bv;
            v.w = acc[i][j + 3] + bv;
            *(float4*)(crow + j) = v;
        }
    }
}

// ---------------------------------------------------------------------------
// Row softmax over 4096 contiguous floats. One 256-thread block per row;
// values held in registers (16 per thread) across max/exp/sum/scale.
// ---------------------------------------------------------------------------
__device__ __forceinline__ float warp_max(float x) {
#pragma unroll
    for (int o = 16; o > 0; o >>= 1) x = fmaxf(x, __shfl_xor_sync(0xffffffffu, x, o));
    return x;
}
__device__ __forceinline__ float warp_sum(float x) {
#pragma unroll
    for (int o = 16; o > 0; o >>= 1) x += __shfl_xor_sync(0xffffffffu, x, o);
    return x;
}

__global__ __launch_bounds__(256)
void softmax_rows(float* __restrict__ att)
{
    const int N = NTOK;
    float* row = att + (long long)blockIdx.x * N;
    const int tid = threadIdx.x;

    float4 v[4];
    float m = -1e30f;
#pragma unroll
    for (int i = 0; i < 4; i++) {
        v[i] = *(const float4*)(row + i * 1024 + tid * 4);
        m = fmaxf(m, fmaxf(fmaxf(v[i].x, v[i].y), fmaxf(v[i].z, v[i].w)));
    }

    __shared__ float sred[8];
    m = warp_max(m);
    if ((tid & 31) == 0) sred[tid >> 5] = m;
    __syncthreads();
    {
        float t = (tid < 8) ? sred[tid & 7] : -1e30f;
        t = warp_max(t);           // all lanes get block max within warp 0 pattern
        m = __shfl_sync(0xffffffffu, t, 0);
    }
    // broadcast block max via smem (warp 0 computed it; others need it)
    if (tid == 0) sred[0] = m;
    __syncthreads();
    m = sred[0];

    float s = 0.f;
#pragma unroll
    for (int i = 0; i < 4; i++) {
        v[i].x = __expf(v[i].x - m);
        v[i].y = __expf(v[i].y - m);
        v[i].z = __expf(v[i].z - m);
        v[i].w = __expf(v[i].w - m);
        s += v[i].x + v[i].y + v[i].z + v[i].w;
    }

    s = warp_sum(s);
    __syncthreads();                 // protect sred reuse
    if ((tid & 31) == 0) sred[tid >> 5] = s;
    __syncthreads();
    {
        float t = (tid < 8) ? sred[tid & 7] : 0.f;
        t = warp_sum(t);
        if (tid == 0) sred[0] = t;
    }
    __syncthreads();
    const float inv = 1.f / sred[0];

#pragma unroll
    for (int i = 0; i < 4; i++) {
        v[i].x *= inv; v[i].y *= inv; v[i].z *= inv; v[i].w *= inv;
        *(float4*)(row + i * 1024 + tid * 4) = v[i];
    }
}

// ---------------------------------------------------------------------------
// Launch
// ---------------------------------------------------------------------------
extern "C" void kernel_launch(void* const* d_in, const int* in_sizes, int n_in,
                              void* d_out, int out_size)
{
    (void)in_sizes; (void)n_in; (void)out_size;
    const float* p  = (const float*)d_in[0];
    const float* bt = (const float*)d_in[1];
    const float* Wq = (const float*)d_in[2];
    const float* bq = (const float*)d_in[3];
    const float* Wk = (const float*)d_in[4];
    const float* bk = (const float*)d_in[5];
    float* out = (float*)d_out;

    void *qp_, *kp_, *ap_;
    cudaGetSymbolAddress(&qp_, g_q);
    cudaGetSymbolAddress(&kp_, g_k);
    cudaGetSymbolAddress(&ap_, g_att);
    float* qp = (float*)qp_;
    float* kp = (float*)kp_;
    float* ap = (float*)ap_;

    const dim3 blk(256);

    // 1) projections:  C[o][n] = sum_c W[o][c] * X[c][n] + bias[o]
    //    A = W (row-major [O][C], K-major), B = X ([C][N], direct), per-batch B/C.
    {
        dim3 g(COUT / TILE, NTOK / TILE, BATCH);                  // (1, 32, 4)
        sgemm_nt<true, false, true><<<g, blk>>>(
            Wq, p, bq, qp, COUT, NTOK, CIN,
            0LL, (long long)CIN * NTOK, (long long)COUT * NTOK);
        sgemm_nt<true, false, true><<<g, blk>>>(
            Wk, bt, bk, kp, COUT, NTOK, CIN,
            0LL, (long long)CIN * NTOK, (long long)COUT * NTOK);
    }

    // 2) energy: E[n][m] = sum_o Q[o][n] * K[o][m]   (both operands direct)
    {
        dim3 g(NTOK / TILE, NTOK / TILE, BATCH);                  // (32, 32, 4)
        sgemm_nt<false, false, false><<<g, blk>>>(
            qp, kp, nullptr, ap, NTOK, NTOK, COUT,
            (long long)COUT * NTOK, (long long)COUT * NTOK,
            (long long)NTOK * NTOK);
    }

    // 3) softmax over last dim (rows of att), all batches flattened
    softmax_rows<<<BATCH * NTOK, blk>>>(ap);

    // 4) out[c][n] = sum_m b[c][m] * att[n][m]   (both operands K-major)
    //    writes directly into [B][C][N] layout, n contiguous.
    {
        dim3 g(CIN / TILE, NTOK / TILE, BATCH);                   // (2, 32, 4)
        sgemm_nt<true, true, false><<<g, blk>>>(
            bt, ap, nullptr, out, CIN, NTOK, NTOK,
            (long long)CIN * NTOK, (long long)NTOK * NTOK,
            (long long)CIN * NTOK);
    }
}

// round 3
// speedup vs baseline: 2.3018x; 2.3018x over previous
#include <cuda_runtime.h>
#include <cuda_bf16.h>
#include <cstdint>

#define BATCH 4
#define CIN   256
#define COUT  128
#define NTOK  4096

// ---------------------------------------------------------------------------
// Scratch (__device__ globals; allocation-free rule)
// ---------------------------------------------------------------------------
__device__ __nv_bfloat16 g_pt_hi[(long long)BATCH * NTOK * CIN];   // p^T [b][n][c]
__device__ __nv_bfloat16 g_pt_lo[(long long)BATCH * NTOK * CIN];
__device__ __nv_bfloat16 g_bt_hi[(long long)BATCH * NTOK * CIN];   // b^T [b][n][c]
__device__ __nv_bfloat16 g_bt_lo[(long long)BATCH * NTOK * CIN];
__device__ __nv_bfloat16 g_wq_hi[COUT * CIN], g_wq_lo[COUT * CIN]; // [o][c]
__device__ __nv_bfloat16 g_wk_hi[COUT * CIN], g_wk_lo[COUT * CIN];
__device__ __nv_bfloat16 g_q_hi[(long long)BATCH * NTOK * COUT];   // [b][n][o]
__device__ __nv_bfloat16 g_q_lo[(long long)BATCH * NTOK * COUT];
__device__ __nv_bfloat16 g_k_hi[(long long)BATCH * NTOK * COUT];   // [b][m][o]
__device__ __nv_bfloat16 g_k_lo[(long long)BATCH * NTOK * COUT];
__device__ float         g_att [(long long)BATCH * NTOK * NTOK];   // fp32 logits
__device__ __nv_bfloat16 g_ah  [(long long)BATCH * NTOK * NTOK];   // softmax hi
__device__ __nv_bfloat16 g_al  [(long long)BATCH * NTOK * NTOK];   // softmax lo
__device__ __nv_bfloat16 g_bv_hi[(long long)BATCH * CIN * NTOK];   // b [b][c][m]
__device__ __nv_bfloat16 g_bv_lo[(long long)BATCH * CIN * NTOK];

// ---------------------------------------------------------------------------
// Helpers (all plain sm_80+-expressible PTX; NO tcgen05 — compute_103 target)
// ---------------------------------------------------------------------------
__device__ __forceinline__ uint32_t smem_u32(const void* p) {
    uint32_t a;
    asm("{ .reg .u64 t; cvta.to.shared.u64 t, %1; cvt.u32.u64 %0, t; }"
        : "=r"(a) : "l"(p));
    return a;
}
__device__ __forceinline__ void cp16(uint32_t dst, const void* src) {
    asm volatile("cp.async.cg.shared.global [%0], [%1], 16;"
                 :: "r"(dst), "l"(src) : "memory");
}
__device__ __forceinline__ void cp_commit() {
    asm volatile("cp.async.commit_group;" ::: "memory");
}
template<int N>
__device__ __forceinline__ void cp_wait() {
    asm volatile("cp.async.wait_group %0;" :: "n"(N) : "memory");
}
__device__ __forceinline__ void ldsm4(uint32_t* r, uint32_t addr) {
    asm volatile("ldmatrix.sync.aligned.m8n8.x4.shared.b16 {%0,%1,%2,%3}, [%4];"
                 : "=r"(r[0]), "=r"(r[1]), "=r"(r[2]), "=r"(r[3]) : "r"(addr));
}
__device__ __forceinline__ void hmma(float* c, const uint32_t* a, const uint32_t* b) {
    asm volatile(
        "mma.sync.aligned.m16n8k16.row.col.f32.bf16.bf16.f32 "
        "{%0,%1,%2,%3}, {%4,%5,%6,%7}, {%8,%9}, {%0,%1,%2,%3};"
        : "+f"(c[0]), "+f"(c[1]), "+f"(c[2]), "+f"(c[3])
        : "r"(a[0]), "r"(a[1]), "r"(a[2]), "r"(a[3]), "r"(b[0]), "r"(b[1]));
}
__device__ __forceinline__ void split2(float x, __nv_bfloat16& h, __nv_bfloat16& l) {
    h = __float2bfloat16(x);
    l = __float2bfloat16(x - __bfloat162float(h));
}

// ---------------------------------------------------------------------------
// Prep kernels
// ---------------------------------------------------------------------------
__global__ void ew_split(const float* __restrict__ in,
                         __nv_bfloat16* __restrict__ hi,
                         __nv_bfloat16* __restrict__ lo, long long n) {
    long long i = (long long)blockIdx.x * blockDim.x + threadIdx.x;
    if (i < n) split2(in[i], hi[i], lo[i]);
}

// in: [z][C][N] fp32 -> out hi/lo [z][N][C] bf16
__global__ void trans_split(const float* __restrict__ in,
                            __nv_bfloat16* __restrict__ hi,
                            __nv_bfloat16* __restrict__ lo, int C, int N) {
    __shared__ float t[32][33];
    long long zoff = (long long)blockIdx.z * C * N;
    const int n0 = blockIdx.x * 32, c0 = blockIdx.y * 32;
    const int tx = threadIdx.x, ty = threadIdx.y;
#pragma unroll
    for (int j = 0; j < 32; j += 8)
        t[ty + j][tx] = in[zoff + (long long)(c0 + ty + j) * N + n0 + tx];
    __syncthreads();
#pragma unroll
    for (int j = 0; j < 32; j += 8) {
        float v = t[tx][ty + j];
        __nv_bfloat16 h, l;
        split2(v, h, l);
        long long o = zoff + (long long)(n0 + ty + j) * C + c0 + tx;
        hi[o] = h; lo[o] = l;
    }
}

// ---------------------------------------------------------------------------
// Softmax over rows of g_att; writes split bf16 probs
// ---------------------------------------------------------------------------
__device__ __forceinline__ float warp_max(float x) {
#pragma unroll
    for (int o = 16; o > 0; o >>= 1) x = fmaxf(x, __shfl_xor_sync(0xffffffffu, x, o));
    return x;
}
__device__ __forceinline__ float warp_sum(float x) {
#pragma unroll
    for (int o = 16; o > 0; o >>= 1) x += __shfl_xor_sync(0xffffffffu, x, o);
    return x;
}

__global__ __launch_bounds__(256)
void softmax_split(const float* __restrict__ att,
                   __nv_bfloat16* __restrict__ ah, __nv_bfloat16* __restrict__ al) {
    const long long ro = (long long)blockIdx.x * NTOK;
    const float* row = att + ro;
    const int tid = threadIdx.x;

    float4 v[4];
    float m = -1e30f;
#pragma unroll
    for (int i = 0; i < 4; i++) {
        v[i] = *(const float4*)(row + i * 1024 + tid * 4);
        m = fmaxf(m, fmaxf(fmaxf(v[i].x, v[i].y), fmaxf(v[i].z, v[i].w)));
    }
    __shared__ float sred[8];
    m = warp_max(m);
    if ((tid & 31) == 0) sred[tid >> 5] = m;
    __syncthreads();
    {
        float t = (tid < 8) ? sred[tid & 7] : -1e30f;
        t = warp_max(t);
        if (tid == 0) sred[0] = t;
    }
    __syncthreads();
    m = sred[0];

    float s = 0.f;
#pragma unroll
    for (int i = 0; i < 4; i++) {
        v[i].x = __expf(v[i].x - m); v[i].y = __expf(v[i].y - m);
        v[i].z = __expf(v[i].z - m); v[i].w = __expf(v[i].w - m);
        s += v[i].x + v[i].y + v[i].z + v[i].w;
    }
    s = warp_sum(s);
    __syncthreads();
    if ((tid & 31) == 0) sred[tid >> 5] = s;
    __syncthreads();
    {
        float t = (tid < 8) ? sred[tid & 7] : 0.f;
        t = warp_sum(t);
        if (tid == 0) sred[0] = t;
    }
    __syncthreads();
    const float inv = 1.f / sred[0];

#pragma unroll
    for (int i = 0; i < 4; i++) {
        float x0 = v[i].x * inv, x1 = v[i].y * inv, x2 = v[i].z * inv, x3 = v[i].w * inv;
        __nv_bfloat16 h0, h1, h2, h3, l0, l1, l2, l3;
        split2(x0, h0, l0); split2(x1, h1, l1);
        split2(x2, h2, l2); split2(x3, h3, l3);
        long long off = ro + i * 1024 + tid * 4;
        ((__nv_bfloat162*)(ah + off))[0] = __halves2bfloat162(h0, h1);
        ((__nv_bfloat162*)(ah + off))[1] = __halves2bfloat162(h2, h3);
        ((__nv_bfloat162*)(al + off))[0] = __halves2bfloat162(l0, l1);
        ((__nv_bfloat162*)(al + off))[1] = __halves2bfloat162(l2, l3);
    }
}

// ---------------------------------------------------------------------------
// Split-bf16 HMMA GEMM:  C[m][n] = sum_k A(m,k)*B(n,k), A/B both K-major.
// D = Ah*Bh + Ah*Bl + Al*Bh (+ Al*Bl if PRODS==4), fp32 accum.
// CTA tile 128x128, 8 warps of 64x32, K-slab 32, cp.async double buffer.
// EPI 0: Cf[m*ldC + n]            (fp32)
// EPI 1: Chi/Clo[m*ldC + n] +bias (split bf16, bias over n)
// EPI 2: Cf[n*ldC + m]            (fp32, transposed store)
// ---------------------------------------------------------------------------
#define KSLAB 32
#define RSTRB 80                        // smem row stride bytes (32 bf16 + pad)
#define ASZ   (128 * RSTRB)             // 10240 B per matrix tile
#define STAGE (4 * ASZ)                 // Ah, Al, Bh, Bl
#define GSMEM (2 * STAGE)               // 81920 B

template<int PRODS, int EPI>
__global__ __launch_bounds__(256)
void gemm_mma(const __nv_bfloat16* __restrict__ Ah, const __nv_bfloat16* __restrict__ Al,
              const __nv_bfloat16* __restrict__ Bh, const __nv_bfloat16* __restrict__ Bl,
              const float* __restrict__ bias,
              float* __restrict__ Cf,
              __nv_bfloat16* __restrict__ Chi, __nv_bfloat16* __restrict__ Clo,
              int K, long long sA, long long sB, long long sC, int ldC)
{
    extern __shared__ char smem[];
    const uint32_t sb = smem_u32(smem);
    const int tid = threadIdx.x, warp = tid >> 5, lane = tid & 31;
    const int wm = warp & 1, wn = warp >> 1;       // 2 x 4 warp grid
    const int m0 = blockIdx.x * 128;
    const int n0 = blockIdx.y * 128;
    const int z  = blockIdx.z;

    Ah += (long long)z * sA;            Al += (long long)z * sA;
    Bh += (long long)z * sB + (long long)n0 * K;
    Bl += (long long)z * sB + (long long)n0 * K;
    if (EPI == 0 || EPI == 2) Cf += (long long)z * sC;
    else { Chi += (long long)z * sC; Clo += (long long)z * sC; }

    float acc[4][4][4];
#pragma unroll
    for (int i = 0; i < 4; i++)
#pragma unroll
        for (int j = 0; j < 4; j++)
#pragma unroll
            for (int r = 0; r < 4; r++) acc[i][j][r] = 0.f;

    auto load_slab = [&](int s, int b) {
        const uint32_t base = sb + (uint32_t)b * STAGE;
        const long long kof = (long long)s * KSLAB;
#pragma unroll
        for (int i = 0; i < 2; i++) {
            const int id = tid + i * 256;          // 0..511
            const int r = id >> 2, g = id & 3;     // row, 16B chunk
            const uint32_t so = base + (uint32_t)(r * RSTRB + g * 16);
            const long long goA = (long long)(m0 + r) * K + kof + g * 8;
            cp16(so,           Ah + goA);
            cp16(so + ASZ,     Al + goA);
            const long long goB = (long long)r * K + kof + g * 8;
            cp16(so + 2 * ASZ, Bh + goB);
            cp16(so + 3 * ASZ, Bl + goB);
        }
    };

    const int NS = K / KSLAB;
    load_slab(0, 0);
    cp_commit();

    // lane-derived ldmatrix source rows
    const int arow = (lane & 7) + ((lane >> 3) & 1) * 8;   // A row within 16
    const int akof = (lane >> 4) * 8;                      // A k offset
    const int brow = lane & 7;                             // B row within 8
    const int bkof = ((lane >> 3) & 1) * 8;                // B k offset
    const int bnt  = (lane >> 4);                          // B sub-tile (0/1)

    for (int s = 0; s < NS; s++) {
        const int buf = s & 1;
        if (s + 1 < NS) { load_slab(s + 1, buf ^ 1); cp_commit(); cp_wait<1>(); }
        else            { cp_wait<0>(); }
        __syncthreads();

        const uint32_t ab = sb + (uint32_t)buf * STAGE;
        const uint32_t bb = ab + 2 * ASZ;

#pragma unroll
        for (int kk = 0; kk < KSLAB; kk += 16) {
            uint32_t a_h[4][4], a_l[4][4], b_h[4][2], b_l[4][2];
#pragma unroll
            for (int mt = 0; mt < 4; mt++) {
                const uint32_t ao = ab +
                    (uint32_t)((wm * 64 + mt * 16 + arow) * RSTRB + (kk + akof) * 2);
                ldsm4(a_h[mt], ao);
                ldsm4(a_l[mt], ao + ASZ);
            }
#pragma unroll
            for (int np = 0; np < 2; np++) {
                const uint32_t bo = bb +
                    (uint32_t)((wn * 32 + np * 16 + bnt * 8 + brow) * RSTRB +
                               (kk + bkof) * 2);
                uint32_t th[4], tl[4];
                ldsm4(th, bo);
                ldsm4(tl, bo + ASZ);
                b_h[np * 2][0] = th[0]; b_h[np * 2][1] = th[1];
                b_h[np * 2 + 1][0] = th[2]; b_h[np * 2 + 1][1] = th[3];
                b_l[np * 2][0] = tl[0]; b_l[np * 2][1] = tl[1];
                b_l[np * 2 + 1][0] = tl[2]; b_l[np * 2 + 1][1] = tl[3];
            }
#pragma unroll
            for (int mt = 0; mt < 4; mt++)
#pragma unroll
                for (int nt = 0; nt < 4; nt++) {
                    hmma(acc[mt][nt], a_h[mt], b_h[nt]);
                    hmma(acc[mt][nt], a_h[mt], b_l[nt]);
                    hmma(acc[mt][nt], a_l[mt], b_h[nt]);
                    if (PRODS == 4) hmma(acc[mt][nt], a_l[mt], b_l[nt]);
                }
        }
        __syncthreads();
    }

    // ---- epilogue ----
    const int mrow = lane >> 2;
    const int ncol = (lane & 3) * 2;
#pragma unroll
    for (int mt = 0; mt < 4; mt++)
#pragma unroll
        for (int nt = 0; nt < 4; nt++) {
            const int m = m0 + wm * 64 + mt * 16 + mrow;
            const int n = n0 + wn * 32 + nt * 8 + ncol;
            const float* c = acc[mt][nt];
            if (EPI == 0) {
                *(float2*)&Cf[(long long)m * ldC + n]       = make_float2(c[0], c[1]);
                *(float2*)&Cf[(long long)(m + 8) * ldC + n] = make_float2(c[2], c[3]);
            } else if (EPI == 1) {
                const float b0 = bias[n], b1 = bias[n + 1];
                __nv_bfloat16 h0, h1, h2, h3, l0, l1, l2, l3;
                split2(c[0] + b0, h0, l0); split2(c[1] + b1, h1, l1);
                split2(c[2] + b0, h2, l2); split2(c[3] + b1, h3, l3);
                *(__nv_bfloat162*)&Chi[(long long)m * ldC + n]       = __halves2bfloat162(h0, h1);
                *(__nv_bfloat162*)&Clo[(long long)m * ldC + n]       = __halves2bfloat162(l0, l1);
                *(__nv_bfloat162*)&Chi[(long long)(m + 8) * ldC + n] = __halves2bfloat162(h2, h3);
                *(__nv_bfloat162*)&Clo[(long long)(m + 8) * ldC + n] = __halves2bfloat162(l2, l3);
            } else {
                Cf[(long long)n * ldC + m]           = c[0];
                Cf[(long long)(n + 1) * ldC + m]     = c[1];
                Cf[(long long)n * ldC + m + 8]       = c[2];
                Cf[(long long)(n + 1) * ldC + m + 8] = c[3];
            }
        }
}

// ---------------------------------------------------------------------------
// Launch
// ---------------------------------------------------------------------------
extern "C" void kernel_launch(void* const* d_in, const int* in_sizes, int n_in,
                              void* d_out, int out_size)
{
    (void)in_sizes; (void)n_in; (void)out_size;
    const float* p  = (const float*)d_in[0];
    const float* bt = (const float*)d_in[1];
    const float* Wq = (const float*)d_in[2];
    const float* bq = (const float*)d_in[3];
    const float* Wk = (const float*)d_in[4];
    const float* bk = (const float*)d_in[5];
    float* out = (float*)d_out;

    auto sym = [](const void* s) { void* a; cudaGetSymbolAddress(&a, s); return a; };
    __nv_bfloat16* pt_hi = (__nv_bfloat16*)sym(g_pt_hi);
    __nv_bfloat16* pt_lo = (__nv_bfloat16*)sym(g_pt_lo);
    __nv_bfloat16* bt_hi = (__nv_bfloat16*)sym(g_bt_hi);
    __nv_bfloat16* bt_lo = (__nv_bfloat16*)sym(g_bt_lo);
    __nv_bfloat16* wq_hi = (__nv_bfloat16*)sym(g_wq_hi);
    __nv_bfloat16* wq_lo = (__nv_bfloat16*)sym(g_wq_lo);
    __nv_bfloat16* wk_hi = (__nv_bfloat16*)sym(g_wk_hi);
    __nv_bfloat16* wk_lo = (__nv_bfloat16*)sym(g_wk_lo);
    __nv_bfloat16* q_hi  = (__nv_bfloat16*)sym(g_q_hi);
    __nv_bfloat16* q_lo  = (__nv_bfloat16*)sym(g_q_lo);
    __nv_bfloat16* k_hi  = (__nv_bfloat16*)sym(g_k_hi);
    __nv_bfloat16* k_lo  = (__nv_bfloat16*)sym(g_k_lo);
    float*         att   = (float*)sym(g_att);
    __nv_bfloat16* ah    = (__nv_bfloat16*)sym(g_ah);
    __nv_bfloat16* al    = (__nv_bfloat16*)sym(g_al);
    __nv_bfloat16* bv_hi = (__nv_bfloat16*)sym(g_bv_hi);
    __nv_bfloat16* bv_lo = (__nv_bfloat16*)sym(g_bv_lo);

    cudaFuncSetAttribute(gemm_mma<4, 1>, cudaFuncAttributeMaxDynamicSharedMemorySize, GSMEM);
    cudaFuncSetAttribute(gemm_mma<4, 0>, cudaFuncAttributeMaxDynamicSharedMemorySize, GSMEM);
    cudaFuncSetAttribute(gemm_mma<3, 2>, cudaFuncAttributeMaxDynamicSharedMemorySize, GSMEM);

    // --- prep: splits + transposes ---
    ew_split<<<(COUT * CIN + 255) / 256, 256>>>(Wq, wq_hi, wq_lo, COUT * CIN);
    ew_split<<<(COUT * CIN + 255) / 256, 256>>>(Wk, wk_hi, wk_lo, COUT * CIN);
    {
        long long n = (long long)BATCH * CIN * NTOK;
        ew_split<<<(int)((n + 255) / 256), 256>>>(bt, bv_hi, bv_lo, n);
    }
    {
        dim3 g(NTOK / 32, CIN / 32, BATCH), b(32, 8);
        trans_split<<<g, b>>>(p,  pt_hi, pt_lo, CIN, NTOK);
        trans_split<<<g, b>>>(bt, bt_hi, bt_lo, CIN, NTOK);
    }

    // --- projections: q[n][o], k[n][o] split bf16 (+bias) ---
    {
        dim3 g(NTOK / 128, COUT / 128, BATCH);                 // (32, 1, 4)
        gemm_mma<4, 1><<<g, 256, GSMEM>>>(
            pt_hi, pt_lo, wq_hi, wq_lo, bq, nullptr, q_hi, q_lo,
            CIN, (long long)NTOK * CIN, 0LL, (long long)NTOK * COUT, COUT);
        gemm_mma<4, 1><<<g, 256, GSMEM>>>(
            bt_hi, bt_lo, wk_hi, wk_lo, bk, nullptr, k_hi, k_lo,
            CIN, (long long)NTOK * CIN, 0LL, (long long)NTOK * COUT, COUT);
    }

    // --- energy: att[n][m] fp32 ---
    {
        dim3 g(NTOK / 128, NTOK / 128, BATCH);                 // (32, 32, 4)
        gemm_mma<4, 0><<<g, 256, GSMEM>>>(
            q_hi, q_lo, k_hi, k_lo, nullptr, att, nullptr, nullptr,
            COUT, (long long)NTOK * COUT, (long long)NTOK * COUT,
            (long long)NTOK * NTOK, NTOK);
    }

    // --- softmax + split ---
    softmax_split<<<BATCH * NTOK, 256>>>(att, ah, al);

    // --- out[c][n] = sum_m att[n][m] * b[c][m]  (transposed store) ---
    {
        dim3 g(NTOK / 128, CIN / 128, BATCH);                  // (32, 2, 4)
        gemm_mma<3, 2><<<g, 256, GSMEM>>>(
            ah, al, bv_hi, bv_lo, nullptr, out, nullptr, nullptr,
            NTOK, (long long)NTOK * NTOK, (long long)CIN * NTOK,
            (long long)CIN * NTOK, NTOK);
    }
}